// round 7
// baseline (speedup 1.0000x reference)
#include <cuda_runtime.h>
#include <stdint.h>

#define SLEN  400000
#define WIN   400
#define NW    1000      // SLEN / WIN
#define NA    3
#define NR    64
#define NB    2
#define KTOP  8
#define NF4   100       // WIN / 4
#define ROWF4 (SLEN / 4)
#define NTILES (NA * NW) // 3000
#define GRID  444        // 148 SMs * 3 CTAs
#define NT_MAX 7
#define FULL7 336        // 3000 - 444*6 blocks get 7 tiles

__device__ __forceinline__ unsigned long long mk_key(float v, int r) {
    unsigned u = __float_as_uint(v);
    u = (u & 0x80000000u) ? ~u : (u | 0x80000000u);   // order-preserving map
    return (((unsigned long long)u) << 6) | (unsigned long long)(63 - r);
}

__global__ __launch_bounds__(256, 3)
void fused_windowed_topk(const float* __restrict__ mixed,
                         const float* __restrict__ ref,
                         const float* __restrict__ weights,
                         float* __restrict__ out,
                         int out_size) {
    __shared__ float4 s_m[NT_MAX][NB][NF4];   // 22400 B
    __shared__ float  s_sc[NT_MAX][NB][NR];   //  3584 B

    const int tid  = threadIdx.x;
    const int warp = tid >> 5;
    const int lane = tid & 31;
    const int bid  = blockIdx.x;

    // truly contiguous tiles: tile = a*NW + w, block owns consecutive w's
    const int cnt   = (bid < FULL7) ? 7 : 6;
    const int tbase = (bid < FULL7) ? bid * 7 : FULL7 * 7 + (bid - FULL7) * 6;

    // ---- Phase 0: stage mixed windows for all my tiles ----
    for (int v = tid; v < cnt * NB * NF4; v += 256) {
        const int i   = v / (NB * NF4);
        const int rem = v % (NB * NF4);
        const int b   = rem / NF4;
        const int j   = rem % NF4;
        const int w   = (tbase + i) % NW;
        s_m[i][b][j] = __ldg((const float4*)(mixed + (size_t)b * SLEN + w * WIN) + j);
    }
    __syncthreads();

    // ---- Phase 1: stream all ref rows for all tiles, no syncs ----
    for (int i = 0; i < cnt; i++) {
        const int tile = tbase + i;
        const int a = tile / NW;
        const int w = tile % NW;

        const float4* rp =
            (const float4*)(ref + ((size_t)a * NR + warp * 8) * SLEN + (size_t)w * WIN);
        float s0[8], s1[8];
#pragma unroll
        for (int rr = 0; rr < 8; rr++) { s0[rr] = 0.f; s1[rr] = 0.f; }

#pragma unroll
        for (int t = 0; t < 3; t++) {
            const int j4 = lane + 32 * t;
            float4 rv[8];
#pragma unroll
            for (int rr = 0; rr < 8; rr++)
                rv[rr] = __ldg(rp + rr * ROWF4 + j4);
            const float4 m0 = s_m[i][0][j4];
            const float4 m1 = s_m[i][1][j4];
#pragma unroll
            for (int rr = 0; rr < 8; rr++) {
                s0[rr] += rv[rr].x * m0.x + rv[rr].y * m0.y + rv[rr].z * m0.z + rv[rr].w * m0.w;
                s1[rr] += rv[rr].x * m1.x + rv[rr].y * m1.y + rv[rr].z * m1.z + rv[rr].w * m1.w;
            }
        }
        // tail: float4 96..99 on lanes 0..3 (same per-lane order as before)
        if (lane < 4) {
            const int j4 = 96 + lane;
            const float4 m0 = s_m[i][0][j4];
            const float4 m1 = s_m[i][1][j4];
#pragma unroll
            for (int rr = 0; rr < 8; rr++) {
                float4 rv = __ldg(rp + rr * ROWF4 + j4);
                s0[rr] += rv.x * m0.x + rv.y * m0.y + rv.z * m0.z + rv.w * m0.w;
                s1[rr] += rv.x * m1.x + rv.y * m1.y + rv.z * m1.z + rv.w * m1.w;
            }
        }

        // ---- multi-value butterfly reduce: 16 sums in 16 shuffles ----
        // Same lane-pair combine order as the xor tree -> bit-identical
        // (validated in R4: identical rel_err).
        float f[16];
#pragma unroll
        for (int rr = 0; rr < 8; rr++) { f[2*rr] = s0[rr]; f[2*rr+1] = s1[rr]; }
#pragma unroll
        for (int off = 16; off >= 2; off >>= 1) {
#pragma unroll
            for (int j = 0; j < 16; j++) {
                if (j < (off >> 1)) {
                    float A = f[j], B = f[j + (off >> 1)];
                    float send = (lane & off) ? A : B;
                    float recv = __shfl_xor_sync(0xffffffffu, send, off);
                    f[j] = ((lane & off) ? B : A) + recv;
                }
            }
        }
        f[0] += __shfl_xor_sync(0xffffffffu, f[0], 1);
        if ((lane & 1) == 0) {
            const int k  = (lane >> 1) & 15;   // sum index held by this lane pair
            const int rr = k >> 1;
            const int bb = k & 1;
            s_sc[i][bb][warp * 8 + rr] = f[0] * (1.0f / WIN);
        }
    }
    __syncthreads();

    // ---- Phase 2: top-k tasks (cnt*NB <= 14) spread over all 8 warps ----
    const bool write_idx = (out_size >= NB * NA * NW * (1 + KTOP));

    for (int task = warp; task < cnt * NB; task += 8) {
        const int i = task >> 1;
        const int b = task & 1;
        const int tile = tbase + i;
        const int a = tile / NW;
        const int w = tile % NW;

        unsigned long long k0 = mk_key(s_sc[i][b][lane], lane);
        unsigned long long k1 = mk_key(s_sc[i][b][lane + 32], lane + 32);

        const int base = (b * NA + a) * NW + w;
        float acc = 0.f;
#pragma unroll
        for (int k = 0; k < KTOP; k++) {
            unsigned long long km = (k0 > k1) ? k0 : k1;
#pragma unroll
            for (int o = 16; o; o >>= 1) {
                unsigned long long other = __shfl_xor_sync(0xffffffffu, km, o);
                if (other > km) km = other;
            }
            const int rsel = 63 - (int)(km & 63ull);
            acc += s_sc[i][b][rsel] * __ldg(weights + k);
            if (rsel < 32) {
                if (lane == rsel) k0 = 0ull;
            } else {
                if (lane == rsel - 32) k1 = 0ull;
            }
            if (lane == 0 && write_idx) {
                out[NB * NA * NW + base * KTOP + k] = (float)rsel;
            }
        }
        if (lane == 0) out[base] = acc;
    }
}

extern "C" void kernel_launch(void* const* d_in, const int* in_sizes, int n_in,
                              void* d_out, int out_size) {
    const float* mixed   = (const float*)d_in[0];   // [2, 400000]
    const float* ref     = (const float*)d_in[1];   // [3, 64, 400000]
    const float* weights = (const float*)d_in[2];   // [8, 1]
    float* out = (float*)d_out;

    fused_windowed_topk<<<GRID, 256>>>(mixed, ref, weights, out, out_size);
}

// round 8
// speedup vs baseline: 1.0685x; 1.0685x over previous
#include <cuda_runtime.h>
#include <stdint.h>

#define SLEN  400000
#define WIN   400
#define NW    1000      // SLEN / WIN
#define NA    3
#define NR    64
#define NB    2
#define KTOP  8
#define ROWF4 (SLEN / 4)    // 100000
#define WF4   100            // float4 per window
#define GW    7              // windows per block
#define KB_PER_A 143         // blocks per ancestry
#define GRID  (NA * KB_PER_A) // 429

__device__ __forceinline__ unsigned long long mk_key(float v, int r) {
    unsigned u = __float_as_uint(v);
    u = (u & 0x80000000u) ? ~u : (u | 0x80000000u);   // order-preserving map
    return (((unsigned long long)u) << 6) | (unsigned long long)(63 - r);
}

__global__ __launch_bounds__(256, 3)
void fused_windowed_topk(const float* __restrict__ mixed,
                         const float* __restrict__ ref,
                         const float* __restrict__ weights,
                         float* __restrict__ out,
                         int out_size) {
    __shared__ float4 s_m[NB][704];        // 7 windows of mixed, padded (22528 B)
    __shared__ float  s_sc[NB][GW][NR];    // scores (3584 B)

    const int tid  = threadIdx.x;
    const int warp = tid >> 5;
    const int lane = tid & 31;

    const int a     = blockIdx.x / KB_PER_A;
    const int kb    = blockIdx.x % KB_PER_A;
    const int wbase = (kb == KB_PER_A - 1) ? (NW - GW) : kb * GW;  // 993 for last
    const int wlo   = (kb == KB_PER_A - 1) ? 1 : 0;   // skip overlapped window

    // ---- Phase 0: stage 7 consecutive mixed windows (contiguous!) ----
    for (int v = tid; v < NB * 704; v += 256) {
        const int b = v / 704, j = v % 704;
        float4 val = make_float4(0.f, 0.f, 0.f, 0.f);
        if (j < GW * WF4)
            val = __ldg((const float4*)(mixed + (size_t)b * SLEN + wbase * WIN) + j);
        s_m[b][j] = val;
    }
    __syncthreads();

    // ---- Phase 1: each warp streams its 8 rows, 11.2 KB sequential per row ----
    for (int rr = 0; rr < 8; rr++) {
        const int row = warp * 8 + rr;
        const float4* rp = (const float4*)ref
                         + (size_t)(a * NR + row) * ROWF4 + (size_t)wbase * WF4;

        float a0[GW], a1[GW];
#pragma unroll
        for (int k = 0; k < GW; k++) { a0[k] = 0.f; a1[k] = 0.f; }

        // consume one float4 (iteration 'it' is compile-time in unrolled loops)
        auto consume = [&](int it, float4 v) {
            const int j4 = it * 32 + lane;
            const float4 m0 = s_m[0][j4];
            const float4 m1 = s_m[1][j4];
            const float d0 = v.x * m0.x + v.y * m0.y + v.z * m0.z + v.w * m0.w;
            const float d1 = v.x * m1.x + v.y * m1.y + v.z * m1.z + v.w * m1.w;
            const int c = it * 32, k = c / WF4, rem = c % WF4;
            if (it == 21) {
                if (lane < 28) { a0[6] += d0; a1[6] += d1; }
            } else if (rem + 32 <= WF4) {
                a0[k] += d0; a1[k] += d1;
            } else {
                const int t = WF4 - rem;
                if (lane < t) { a0[k]   += d0; a1[k]   += d1; }
                else          { a0[k+1] += d0; a1[k+1] += d1; }
            }
        };

        float4 rv[8];
        // burst A: its 0..7 (4 KB in flight, sequential)
#pragma unroll
        for (int q = 0; q < 8; q++) rv[q] = __ldg(rp + q * 32 + lane);
#pragma unroll
        for (int q = 0; q < 8; q++) consume(q, rv[q]);
        // burst B: its 8..15
#pragma unroll
        for (int q = 0; q < 8; q++) rv[q] = __ldg(rp + (8 + q) * 32 + lane);
#pragma unroll
        for (int q = 0; q < 8; q++) consume(8 + q, rv[q]);
        // burst C: its 16..21 (it 21: only lanes 0..27 valid)
#pragma unroll
        for (int q = 0; q < 6; q++) {
            if (16 + q == 21) {
                rv[q] = (lane < 28) ? __ldg(rp + 21 * 32 + lane)
                                    : make_float4(0.f, 0.f, 0.f, 0.f);
            } else {
                rv[q] = __ldg(rp + (16 + q) * 32 + lane);
            }
        }
#pragma unroll
        for (int q = 0; q < 6; q++) consume(16 + q, rv[q]);

        // ---- 16-value butterfly reduce (14 real sums + 2 pad) ----
        float f[16];
#pragma unroll
        for (int k = 0; k < GW; k++) { f[2*k] = a0[k]; f[2*k+1] = a1[k]; }
        f[14] = 0.f; f[15] = 0.f;
#pragma unroll
        for (int off = 16; off >= 2; off >>= 1) {
#pragma unroll
            for (int j = 0; j < 16; j++) {
                if (j < (off >> 1)) {
                    float A = f[j], B = f[j + (off >> 1)];
                    float send = (lane & off) ? A : B;
                    float recv = __shfl_xor_sync(0xffffffffu, send, off);
                    f[j] = ((lane & off) ? B : A) + recv;
                }
            }
        }
        f[0] += __shfl_xor_sync(0xffffffffu, f[0], 1);
        if ((lane & 1) == 0) {
            const int p = (lane >> 1) & 15;
            if (p < 2 * GW) {
                const int wl = p >> 1, bb = p & 1;
                s_sc[bb][wl][row] = f[0] * (1.0f / WIN);
            }
        }
    }
    __syncthreads();

    // ---- Phase 2: top-k tasks (up to 14) spread over 8 warps ----
    const bool write_idx = (out_size >= NB * NA * NW * (1 + KTOP));

    for (int task = warp; task < 2 * GW; task += 8) {
        const int wl = task >> 1;
        const int b  = task & 1;
        if (wl < wlo) continue;
        const int w = wbase + wl;
        const float* sc = &s_sc[b][wl][0];

        unsigned long long k0 = mk_key(sc[lane], lane);
        unsigned long long k1 = mk_key(sc[lane + 32], lane + 32);

        const int base = (b * NA + a) * NW + w;
        float acc = 0.f;
#pragma unroll
        for (int k = 0; k < KTOP; k++) {
            unsigned long long km = (k0 > k1) ? k0 : k1;
#pragma unroll
            for (int o = 16; o; o >>= 1) {
                unsigned long long other = __shfl_xor_sync(0xffffffffu, km, o);
                if (other > km) km = other;
            }
            const int rsel = 63 - (int)(km & 63ull);
            acc += sc[rsel] * __ldg(weights + k);
            if (rsel < 32) {
                if (lane == rsel) k0 = 0ull;
            } else {
                if (lane == rsel - 32) k1 = 0ull;
            }
            if (lane == 0 && write_idx) {
                out[NB * NA * NW + base * KTOP + k] = (float)rsel;
            }
        }
        if (lane == 0) out[base] = acc;
    }
}

extern "C" void kernel_launch(void* const* d_in, const int* in_sizes, int n_in,
                              void* d_out, int out_size) {
    const float* mixed   = (const float*)d_in[0];   // [2, 400000]
    const float* ref     = (const float*)d_in[1];   // [3, 64, 400000]
    const float* weights = (const float*)d_in[2];   // [8, 1]
    float* out = (float*)d_out;

    fused_windowed_topk<<<GRID, 256>>>(mixed, ref, weights, out, out_size);
}